// round 10
// baseline (speedup 1.0000x reference)
#include <cuda_runtime.h>
#include <cuda_bf16.h>

// out[i,c] = sum_k (neigh[i,k]>=0 ? data[neigh[i,k],c] : 0) * w[k,c]
// N=200000, K=27, C=64.
// QP=2, TPB=128 (R7 winner) with BRANCHLESS gathers: idx clamped to 0,
// weight zeroed by SEL when invalid. Straight-line body lets ptxas batch
// all independent LDGs -> high MLP -> drives L1/L2 toward saturation.
// data[0]'s row is permanently L1-hot, so clamped loads are ~free.

#define KK 27
#define CV 16          // C/4 float4 per row
#define QP 2           // points per thread
#define TPB 128
#define GRPS 8         // TPB/16 thread groups
#define PTSBLK 16      // GRPS * QP
#define NPAD 28        // padded ints per point row (16B aligned)

#define FMA4(ACC, D, W) \
    ACC.x = fmaf(D.x, W.x, ACC.x); \
    ACC.y = fmaf(D.y, W.y, ACC.y); \
    ACC.z = fmaf(D.z, W.z, ACC.z); \
    ACC.w = fmaf(D.w, W.w, ACC.w);

#define GSTEP(K, COMP) \
    { \
        const float4 wv = __ldg(w4g + (K) * CV + lane); \
        const int a0 = i0.COMP, a1 = i1.COMP; \
        const float4 d0 = __ldg(data + (unsigned)(a0 < 0 ? 0 : a0) * CV + lane); \
        const float4 d1 = __ldg(data + (unsigned)(a1 < 0 ? 0 : a1) * CV + lane); \
        float4 w0, w1; \
        w0.x = a0 < 0 ? 0.f : wv.x;  w0.y = a0 < 0 ? 0.f : wv.y; \
        w0.z = a0 < 0 ? 0.f : wv.z;  w0.w = a0 < 0 ? 0.f : wv.w; \
        w1.x = a1 < 0 ? 0.f : wv.x;  w1.y = a1 < 0 ? 0.f : wv.y; \
        w1.z = a1 < 0 ? 0.f : wv.z;  w1.w = a1 < 0 ? 0.f : wv.w; \
        FMA4(acc0, d0, w0) \
        FMA4(acc1, d1, w1) \
    }

__global__ __launch_bounds__(TPB)
void octree_dwconv_kernel(const float4* __restrict__ data,    // [N][16] float4
                          const float4* __restrict__ w4g,     // [27*16] float4
                          const int*    __restrict__ neigh,   // [N][27]
                          float4*       __restrict__ out)     // [N][16]
{
    __shared__ int s_n[PTSBLK * NPAD];    // 16*28*4 = 1792 B

    const int tid  = threadIdx.x;
    const int base = blockIdx.x * PTSBLK;

    // Stage 16*27 neighbor indices into padded layout [16][28]
    #pragma unroll
    for (int i = tid; i < PTSBLK * KK; i += TPB) {
        const int p = i / KK;
        const int k = i - p * KK;
        s_n[p * NPAD + k] = neigh[base * KK + i];
    }
    __syncthreads();

    const int lane = tid & 15;       // float4 column 0..15
    const int g    = tid >> 4;       // group 0..7
    const int p0   = g * QP;         // local point base

    const int4* s_n4 = reinterpret_cast<const int4*>(s_n);   // [16][7]

    float4 acc0 = make_float4(0.f, 0.f, 0.f, 0.f);
    float4 acc1 = acc0;

    #pragma unroll
    for (int kc = 0; kc < 7; kc++) {
        const int4 i0 = s_n4[(p0 + 0) * 7 + kc];
        const int4 i1 = s_n4[(p0 + 1) * 7 + kc];

        const int kb = kc * 4;
        GSTEP(kb + 0, x)
        GSTEP(kb + 1, y)
        GSTEP(kb + 2, z)
        if (kc < 6) {            // k = 27 doesn't exist (27 = 6*4 + 3)
            GSTEP(kb + 3, w)
        }
    }

    const unsigned ob = (unsigned)(base + p0) * CV + lane;
    out[ob + 0 * CV] = acc0;
    out[ob + 1 * CV] = acc1;
}

extern "C" void kernel_launch(void* const* d_in, const int* in_sizes, int n_in,
                              void* d_out, int out_size) {
    const float4* data    = (const float4*)d_in[0];   // [N,64] fp32
    const float4* w4g     = (const float4*)d_in[1];   // [27,1,64] fp32
    const int*    neigh   = (const int*)d_in[2];      // [N,27] int32
    float4* out = (float4*)d_out;

    const int N = in_sizes[0] / 64;                   // 200000
    const int grid = (N + PTSBLK - 1) / PTSBLK;       // 12500

    octree_dwconv_kernel<<<grid, TPB>>>(data, w4g, neigh, out);
}